// round 1
// baseline (speedup 1.0000x reference)
#include <cuda_runtime.h>
#include <math.h>

#define BB 32
#define LK 4096
#define HH 512

// ---------------- scratch (device globals; no allocations allowed) ----------
__device__ float g_qc[BB * HH];        // Wa q + Wa_b + Ua_b, per (b,h)
__device__ float g_Uat[HH * HH];       // Ua_w transposed: Uat[k*H + n] = Ua_w[n*H + k]
__device__ float g_scores[BB * LK];    // masked scores
__device__ float g_part[8 * BB * HH];  // context partials per l-chunk
__device__ float g_wbuf[BB * LK];      // fallback weights output
__device__ float g_cbuf[BB * HH];      // fallback context output

// ---------------- 1) transpose Ua_w ----------------------------------------
__global__ void k_trans(const float* __restrict__ Ua_w) {
    __shared__ float t[32][33];
    int bx = blockIdx.x * 32, by = blockIdx.y * 32;
    int txx = threadIdx.x, tyy = threadIdx.y;
    #pragma unroll
    for (int i = 0; i < 32; i += 8)
        t[tyy + i][txx] = Ua_w[(size_t)(by + tyy + i) * HH + bx + txx];
    __syncthreads();
    int ox = by + txx;  // n
    int oy = bx + tyy;  // k
    #pragma unroll
    for (int i = 0; i < 32; i += 8)
        g_Uat[(size_t)(oy + i) * HH + ox] = t[txx][tyy + i];
}

// ---------------- 2) q projection (+ bias folding) --------------------------
__global__ void k_qc(const float* __restrict__ query, const float* __restrict__ Wa_w,
                     const float* __restrict__ Wa_b, const float* __restrict__ Ua_b) {
    __shared__ float qs[HH];
    int b = blockIdx.x, h = threadIdx.x;
    qs[h] = query[b * HH + h];
    __syncthreads();
    float acc = 0.f;
    const float* wr = Wa_w + (size_t)h * HH;
    #pragma unroll 8
    for (int j = 0; j < HH; j++) acc += qs[j] * wr[j];
    g_qc[b * HH + h] = acc + Wa_b[h] + Ua_b[h];
}

// ---------------- 3) fused GEMM + tanh + Va dot + mask ----------------------
// C[l, n] = keys[b,l,:] . Ua_w[n,:]   (A: 128x32 tiles, B: 32x64 k-major tiles)
// score[l] = (sum_n tanh(C + qc) * Va_w[n] + Va_b) / T, masked by valid_src_len
__global__ __launch_bounds__(256) void k_score(
    const float* __restrict__ keys, const float* __restrict__ Va_w,
    const float* __restrict__ Va_b, const float* __restrict__ temp,
    const int* __restrict__ valid) {
    __shared__ float As[128][36];   // row-major A tile (padded)
    __shared__ float Bs[32][64];    // k-outer B tile
    __shared__ float red[128][17];

    int b  = blockIdx.x >> 5;             // 32 tiles of 128 rows per batch
    int l0 = (blockIdx.x & 31) * 128;
    int v  = valid[b];
    int tid = threadIdx.x;

    if (l0 >= v) {                        // fully-masked tile: skip all compute
        if (tid < 128) g_scores[b * LK + l0 + tid] = -1e9f;
        return;
    }

    int tx = tid & 15;                    // n micro: 4 cols
    int ty = tid >> 4;                    // m micro: 8 rows
    const float* Abase = keys + ((size_t)b * LK + l0) * HH;

    float sc[8];
    #pragma unroll
    for (int i = 0; i < 8; i++) sc[i] = 0.f;

    for (int nt = 0; nt < HH; nt += 64) {
        float acc[8][4];
        #pragma unroll
        for (int i = 0; i < 8; i++)
            #pragma unroll
            for (int j = 0; j < 4; j++) acc[i][j] = 0.f;

        for (int kt = 0; kt < HH; kt += 32) {
            __syncthreads();
            // A tile: 128x32 floats = 1024 float4, 4 per thread
            #pragma unroll
            for (int r = 0; r < 4; r++) {
                int f = tid + 256 * r;
                int m = f >> 3, k4 = (f & 7) << 2;
                float4 vv = *(const float4*)(Abase + (size_t)m * HH + kt + k4);
                *(float4*)&As[m][k4] = vv;
            }
            // B tile: 32x64 floats = 512 float4, 2 per thread (from transposed Ua)
            #pragma unroll
            for (int r = 0; r < 2; r++) {
                int f = tid + 256 * r;
                int k = f >> 4, n4 = (f & 15) << 2;
                *(float4*)&Bs[k][n4] =
                    *(const float4*)(g_Uat + (size_t)(kt + k) * HH + nt + n4);
            }
            __syncthreads();

            #pragma unroll
            for (int kk = 0; kk < 32; kk++) {
                float4 bv = *(const float4*)&Bs[kk][tx * 4];
                float a[8];
                #pragma unroll
                for (int i = 0; i < 8; i++) a[i] = As[ty * 8 + i][kk];
                #pragma unroll
                for (int i = 0; i < 8; i++) {
                    acc[i][0] += a[i] * bv.x;
                    acc[i][1] += a[i] * bv.y;
                    acc[i][2] += a[i] * bv.z;
                    acc[i][3] += a[i] * bv.w;
                }
            }
        }
        // epilogue for this 64-wide n tile
        #pragma unroll
        for (int j = 0; j < 4; j++) {
            int n = nt + tx * 4 + j;
            float qv = g_qc[b * HH + n];
            float vw = Va_w[n];
            #pragma unroll
            for (int i = 0; i < 8; i++)
                sc[i] += tanhf(acc[i][j] + qv) * vw;
        }
    }

    #pragma unroll
    for (int i = 0; i < 8; i++) red[ty * 8 + i][tx] = sc[i];
    __syncthreads();
    if (tid < 128) {
        float s = 0.f;
        #pragma unroll
        for (int j = 0; j < 16; j++) s += red[tid][j];
        s = (s + Va_b[0]) / temp[0];
        int l = l0 + tid;
        if (l >= v) s = -1e9f;
        g_scores[b * LK + l] = s;
    }
}

// ---------------- 4) softmax over Lk per batch -------------------------------
__global__ void k_softmax(float* __restrict__ w_out) {
    __shared__ float se[LK];
    __shared__ float rbuf[256];
    int b = blockIdx.x, tid = threadIdx.x;
    const float* sc = g_scores + (size_t)b * LK;
    float mx = -1e30f;
    for (int l = tid; l < LK; l += 256) { float vv = sc[l]; se[l] = vv; mx = fmaxf(mx, vv); }
    rbuf[tid] = mx; __syncthreads();
    for (int s = 128; s > 0; s >>= 1) {
        if (tid < s) rbuf[tid] = fmaxf(rbuf[tid], rbuf[tid + s]);
        __syncthreads();
    }
    mx = rbuf[0]; __syncthreads();
    float sum = 0.f;
    for (int l = tid; l < LK; l += 256) { float e = expf(se[l] - mx); se[l] = e; sum += e; }
    rbuf[tid] = sum; __syncthreads();
    for (int s = 128; s > 0; s >>= 1) {
        if (tid < s) rbuf[tid] += rbuf[tid + s];
        __syncthreads();
    }
    float inv = 1.f / rbuf[0];
    for (int l = tid; l < LK; l += 256) w_out[(size_t)b * LK + l] = se[l] * inv;
}

// ---------------- 5) context partials (no atomics -> deterministic) ----------
__global__ void k_ctx(const float* __restrict__ keys, const float* __restrict__ w,
                      const int* __restrict__ valid) {
    __shared__ float ws[512];
    int b = blockIdx.y;
    int chunk = blockIdx.x;
    int lbase = chunk * 512;
    int h = threadIdx.x;
    int v = valid[b];
    float acc = 0.f;
    if (lbase < v) {
        int lend = min(512, v - lbase);
        ws[h] = w[(size_t)b * LK + lbase + h];
        __syncthreads();
        const float* kb = keys + ((size_t)b * LK + lbase) * HH + h;
        for (int l = 0; l < lend; l++) acc += ws[l] * kb[(size_t)l * HH];
    }
    g_part[((size_t)chunk * BB + b) * HH + h] = acc;
}

// ---------------- 6) reduce partials -> context ------------------------------
__global__ void k_ctxred(float* __restrict__ ctx_out) {
    int b = blockIdx.x, h = threadIdx.x;
    float s = 0.f;
    #pragma unroll
    for (int c = 0; c < 8; c++) s += g_part[((size_t)c * BB + b) * HH + h];
    ctx_out[b * HH + h] = s;
}

// ---------------- launch ------------------------------------------------------
extern "C" void kernel_launch(void* const* d_in, const int* in_sizes, int n_in,
                              void* d_out, int out_size) {
    const float* query = (const float*)d_in[0];
    const float* keys  = (const float*)d_in[1];
    const float* Wa_w  = (const float*)d_in[2];
    const float* Wa_b  = (const float*)d_in[3];
    const float* Ua_w  = (const float*)d_in[4];
    const float* Ua_b  = (const float*)d_in[5];
    const float* Va_w  = (const float*)d_in[6];
    const float* Va_b  = (const float*)d_in[7];
    const float* temp  = (const float*)d_in[8];
    const int*   valid = (const int*)d_in[9];

    float* out = (float*)d_out;
    float* ctx_out;
    float* w_out;
    void *cb = nullptr, *wb = nullptr;
    cudaGetSymbolAddress(&cb, g_cbuf);
    cudaGetSymbolAddress(&wb, g_wbuf);
    if (out_size >= BB * HH + BB * LK) { ctx_out = out; w_out = out + BB * HH; }
    else if (out_size == BB * LK)      { w_out = out; ctx_out = (float*)cb; }
    else                               { ctx_out = out; w_out = (float*)wb; }

    k_trans<<<dim3(HH / 32, HH / 32), dim3(32, 8)>>>(Ua_w);
    k_qc<<<BB, HH>>>(query, Wa_w, Wa_b, Ua_b);
    k_score<<<BB * (LK / 128), 256>>>(keys, Va_w, Va_b, temp, valid);
    k_softmax<<<BB, 256>>>(w_out);
    k_ctx<<<dim3(LK / 512, BB), 512>>>(keys, w_out, valid);
    k_ctxred<<<BB, HH>>>(ctx_out);
}

// round 3
// speedup vs baseline: 2.4120x; 2.4120x over previous
#include <cuda_runtime.h>
#include <cstdint>
#include <math.h>

#define BB 32
#define LK 4096
#define HH 512
#define SAS 36                 // padded smem row stride in words

// ---------------- scratch (device globals; no allocations allowed) ----------
__device__ float g_qc[BB * HH];         // Wa q + Wa_b + Ua_b
__device__ float g_spart[4 * BB * LK];  // per-nchunk partial scores
__device__ float g_part[8 * BB * HH];   // context partials per l-chunk
__device__ float g_wbuf[BB * LK];       // fallback weights output
__device__ float g_cbuf[BB * HH];       // fallback context output

// ================= helpers ===================================================
__device__ __forceinline__ uint32_t f2tf(float x) {
    uint32_t r; asm("cvt.rna.tf32.f32 %0, %1;" : "=r"(r) : "f"(x)); return r;
}
__device__ __forceinline__ float fast_tanh(float x) {
    float cx = fminf(fmaxf(x, -15.f), 15.f);
    float e; asm("ex2.approx.f32 %0, %1;" : "=f"(e) : "f"(cx * 2.885390082f));
    float r; asm("rcp.approx.f32 %0, %1;" : "=f"(r) : "f"(e + 1.f));
    return (e - 1.f) * r;
}
#define MMA_TF32(d, a, b)                                                     \
    asm volatile(                                                             \
        "mma.sync.aligned.m16n8k8.row.col.f32.tf32.tf32.f32 "                 \
        "{%0,%1,%2,%3}, {%4,%5,%6,%7}, {%8,%9}, {%0,%1,%2,%3};"               \
        : "+f"((d)[0]), "+f"((d)[1]), "+f"((d)[2]), "+f"((d)[3])              \
        : "r"((a)[0]), "r"((a)[1]), "r"((a)[2]), "r"((a)[3]),                 \
          "r"((b)[0]), "r"((b)[1]))

// ---------------- 1) q projection (+ bias folding) --------------------------
__global__ void k_qc(const float* __restrict__ query, const float* __restrict__ Wa_w,
                     const float* __restrict__ Wa_b, const float* __restrict__ Ua_b) {
    __shared__ float qs[HH];
    int b = blockIdx.x, h = threadIdx.x;
    qs[h] = query[b * HH + h];
    __syncthreads();
    float acc = 0.f;
    const float* wr = Wa_w + (size_t)h * HH;
    #pragma unroll 8
    for (int j = 0; j < HH; j++) acc += qs[j] * wr[j];
    g_qc[b * HH + h] = acc + Wa_b[h] + Ua_b[h];
}

// ---------------- 2) tf32 mma.sync GEMM + tanh + Va partial ------------------
// CTA: 128 l-rows x 128 n-cols (n-chunk z), K=512.
// g_spart[z][b][l] = sum_{n in chunk} tanh(D[l,n] + qc[n]) * Va_w[n]
__global__ __launch_bounds__(256) void k_score_mma(
    const float* __restrict__ keys, const float* __restrict__ Ua_w,
    const float* __restrict__ Va_w, const int* __restrict__ valid) {
    extern __shared__ uint32_t sm[];
    // words: A0@0(4608) B0@4608 A1@9216 B1@13824 qc@18432 va@18560 red@18688
    int lt = blockIdx.x, b = blockIdx.y, z = blockIdx.z;
    int l0 = lt * 128;
    int v = valid[b];
    if (l0 >= v) return;                 // fully-masked tile: no work, no writes

    int tid = threadIdx.x;
    int wid = tid >> 5, lane = tid & 31;
    int mw = wid & 3, nw = wid >> 2;     // warp grid 4(M) x 2(N)
    int g = lane >> 2, tig = lane & 3;
    int n0 = z * 128;

    float* qc_s = (float*)(sm + 18432);
    float* va_s = (float*)(sm + 18560);
    float* red  = (float*)(sm + 18688);
    if (tid < 128) {
        qc_s[tid] = g_qc[b * HH + n0 + tid];
        va_s[tid] = Va_w[n0 + tid];
    }

    const float* Ab = keys + ((size_t)b * LK + l0) * HH;
    const float* Bb = Ua_w + (size_t)n0 * HH;
    int m8 = tid >> 3, kq = tid & 7;     // row-base / quad within row for staging

    float4 pa[4], pb[4];
    float d[2][8][4];
    #pragma unroll
    for (int mi = 0; mi < 2; mi++)
        #pragma unroll
        for (int ni = 0; ni < 8; ni++)
            #pragma unroll
            for (int jj = 0; jj < 4; jj++) d[mi][ni][jj] = 0.f;

    // prefetch stage 0
    #pragma unroll
    for (int r = 0; r < 4; r++) {
        pa[r] = *(const float4*)(Ab + (size_t)(m8 + 32 * r) * HH + kq * 4);
        pb[r] = *(const float4*)(Bb + (size_t)(m8 + 32 * r) * HH + kq * 4);
    }
    #pragma unroll
    for (int r = 0; r < 4; r++) {
        int base = (m8 + 32 * r) * SAS + kq * 4;
        *(uint4*)(sm + base) =
            make_uint4(f2tf(pa[r].x), f2tf(pa[r].y), f2tf(pa[r].z), f2tf(pa[r].w));
        *(uint4*)(sm + 4608 + base) =
            make_uint4(f2tf(pb[r].x), f2tf(pb[r].y), f2tf(pb[r].z), f2tf(pb[r].w));
    }
    __syncthreads();

    for (int kt = 0; kt < 16; kt++) {
        int cur = kt & 1;
        if (kt < 15) {
            int kp = (kt + 1) * 32;
            #pragma unroll
            for (int r = 0; r < 4; r++) {
                pa[r] = *(const float4*)(Ab + (size_t)(m8 + 32 * r) * HH + kp + kq * 4);
                pb[r] = *(const float4*)(Bb + (size_t)(m8 + 32 * r) * HH + kp + kq * 4);
            }
        }
        const uint32_t* As = sm + cur * 9216;
        const uint32_t* Bs = As + 4608;
        #pragma unroll
        for (int k8 = 0; k8 < 4; k8++) {
            int kb = k8 * 8;
            uint32_t a[2][4], bf[8][2];
            #pragma unroll
            for (int mi = 0; mi < 2; mi++) {
                int r = mw * 32 + mi * 16 + g;
                a[mi][0] = As[r * SAS + kb + tig];
                a[mi][1] = As[(r + 8) * SAS + kb + tig];
                a[mi][2] = As[r * SAS + kb + tig + 4];
                a[mi][3] = As[(r + 8) * SAS + kb + tig + 4];
            }
            #pragma unroll
            for (int ni = 0; ni < 8; ni++) {
                int n = nw * 64 + ni * 8 + g;
                bf[ni][0] = Bs[n * SAS + kb + tig];
                bf[ni][1] = Bs[n * SAS + kb + tig + 4];
            }
            #pragma unroll
            for (int mi = 0; mi < 2; mi++)
                #pragma unroll
                for (int ni = 0; ni < 8; ni++)
                    MMA_TF32(d[mi][ni], a[mi], bf[ni]);
        }
        if (kt < 15) {
            __syncthreads();
            uint32_t* An = sm + (1 - cur) * 9216;
            #pragma unroll
            for (int r = 0; r < 4; r++) {
                int base = (m8 + 32 * r) * SAS + kq * 4;
                *(uint4*)(An + base) =
                    make_uint4(f2tf(pa[r].x), f2tf(pa[r].y), f2tf(pa[r].z), f2tf(pa[r].w));
                *(uint4*)(An + 4608 + base) =
                    make_uint4(f2tf(pb[r].x), f2tf(pb[r].y), f2tf(pb[r].z), f2tf(pb[r].w));
            }
            __syncthreads();
        }
    }

    // ---- epilogue: tanh + Va dot, reduce across n ---------------------------
    float rs[2][2] = {{0.f, 0.f}, {0.f, 0.f}};
    #pragma unroll
    for (int mi = 0; mi < 2; mi++)
        #pragma unroll
        for (int ni = 0; ni < 8; ni++)
            #pragma unroll
            for (int jj = 0; jj < 4; jj++) {
                int nl = nw * 64 + ni * 8 + tig * 2 + (jj & 1);
                rs[mi][jj >> 1] += fast_tanh(d[mi][ni][jj] + qc_s[nl]) * va_s[nl];
            }
    #pragma unroll
    for (int mi = 0; mi < 2; mi++)
        #pragma unroll
        for (int hh = 0; hh < 2; hh++) {
            float s = rs[mi][hh];
            s += __shfl_xor_sync(0xffffffffu, s, 1);
            s += __shfl_xor_sync(0xffffffffu, s, 2);
            rs[mi][hh] = s;
        }
    if (tig == 0) {
        #pragma unroll
        for (int mi = 0; mi < 2; mi++)
            #pragma unroll
            for (int hh = 0; hh < 2; hh++) {
                int row = mw * 32 + mi * 16 + hh * 8 + g;
                red[row * 2 + nw] = rs[mi][hh];
            }
    }
    __syncthreads();
    if (tid < 128)
        g_spart[((size_t)z * BB + b) * LK + l0 + tid] = red[tid * 2] + red[tid * 2 + 1];
}

// ---------------- 3) softmax over Lk per batch (sums 4 partials) -------------
__global__ void k_softmax(const float* __restrict__ Va_b, const float* __restrict__ temp,
                          const int* __restrict__ valid, float* __restrict__ w_out) {
    __shared__ float se[LK];
    __shared__ float rbuf[256];
    int b = blockIdx.x, tid = threadIdx.x;
    int v = valid[b];
    float vb = Va_b[0], invT = 1.f / temp[0];
    const float* p0 = g_spart + ((size_t)0 * BB + b) * LK;
    const float* p1 = g_spart + ((size_t)1 * BB + b) * LK;
    const float* p2 = g_spart + ((size_t)2 * BB + b) * LK;
    const float* p3 = g_spart + ((size_t)3 * BB + b) * LK;
    float mx = -1e30f;
    for (int l = tid; l < LK; l += 256) {
        float s = (l < v) ? (p0[l] + p1[l] + p2[l] + p3[l] + vb) * invT : -1e9f;
        se[l] = s; mx = fmaxf(mx, s);
    }
    rbuf[tid] = mx; __syncthreads();
    for (int s = 128; s > 0; s >>= 1) {
        if (tid < s) rbuf[tid] = fmaxf(rbuf[tid], rbuf[tid + s]);
        __syncthreads();
    }
    mx = rbuf[0]; __syncthreads();
    float sum = 0.f;
    for (int l = tid; l < LK; l += 256) { float e = expf(se[l] - mx); se[l] = e; sum += e; }
    rbuf[tid] = sum; __syncthreads();
    for (int s = 128; s > 0; s >>= 1) {
        if (tid < s) rbuf[tid] += rbuf[tid + s];
        __syncthreads();
    }
    float inv = 1.f / rbuf[0];
    for (int l = tid; l < LK; l += 256) w_out[(size_t)b * LK + l] = se[l] * inv;
}

// ---------------- 4) context partials (no atomics -> deterministic) ----------
__global__ void k_ctx(const float* __restrict__ keys, const float* __restrict__ w,
                      const int* __restrict__ valid) {
    __shared__ float ws[512];
    int b = blockIdx.y;
    int chunk = blockIdx.x;
    int lbase = chunk * 512;
    int h = threadIdx.x;
    int v = valid[b];
    float acc = 0.f;
    if (lbase < v) {
        int lend = min(512, v - lbase);
        ws[h] = w[(size_t)b * LK + lbase + h];
        __syncthreads();
        const float* kb = keys + ((size_t)b * LK + lbase) * HH + h;
        for (int l = 0; l < lend; l++) acc += ws[l] * kb[(size_t)l * HH];
    }
    g_part[((size_t)chunk * BB + b) * HH + h] = acc;
}

// ---------------- 5) reduce partials -> context ------------------------------
__global__ void k_ctxred(float* __restrict__ ctx_out) {
    int b = blockIdx.x, h = threadIdx.x;
    float s = 0.f;
    #pragma unroll
    for (int c = 0; c < 8; c++) s += g_part[((size_t)c * BB + b) * HH + h];
    ctx_out[b * HH + h] = s;
}

// ---------------- launch ------------------------------------------------------
extern "C" void kernel_launch(void* const* d_in, const int* in_sizes, int n_in,
                              void* d_out, int out_size) {
    const float* query = (const float*)d_in[0];
    const float* keys  = (const float*)d_in[1];
    const float* Wa_w  = (const float*)d_in[2];
    const float* Wa_b  = (const float*)d_in[3];
    const float* Ua_w  = (const float*)d_in[4];
    const float* Ua_b  = (const float*)d_in[5];
    const float* Va_w  = (const float*)d_in[6];
    const float* Va_b  = (const float*)d_in[7];
    const float* temp  = (const float*)d_in[8];
    const int*   valid = (const int*)d_in[9];

    float* out = (float*)d_out;
    float* ctx_out;
    float* w_out;
    void *cb = nullptr, *wb = nullptr;
    cudaGetSymbolAddress(&cb, g_cbuf);
    cudaGetSymbolAddress(&wb, g_wbuf);
    if (out_size >= BB * HH + BB * LK) { ctx_out = out; w_out = out + BB * HH; }
    else if (out_size == BB * LK)      { w_out = out; ctx_out = (float*)cb; }
    else                               { ctx_out = out; w_out = (float*)wb; }

    static int smem_set = 0;
    const int SMEM_SCORE = (18688 + 256) * 4;   // 75776 B
    if (!smem_set) {
        cudaFuncSetAttribute(k_score_mma, cudaFuncAttributeMaxDynamicSharedMemorySize,
                             SMEM_SCORE);
        smem_set = 1;
    }

    k_qc<<<BB, HH>>>(query, Wa_w, Wa_b, Ua_b);
    k_score_mma<<<dim3(LK / 128, BB, 4), 256, SMEM_SCORE>>>(keys, Ua_w, Va_w, valid);
    k_softmax<<<BB, 256>>>(Va_b, temp, valid, w_out);
    k_ctx<<<dim3(LK / 512, BB), 512>>>(keys, w_out, valid);
    k_ctxred<<<BB, HH>>>(ctx_out);
}

// round 6
// speedup vs baseline: 2.8359x; 1.1757x over previous
#include <cuda_runtime.h>
#include <cstdint>
#include <math.h>

#define BB 32
#define LK 4096
#define HH 512

// ---------------- scratch (device globals; no allocations allowed) ----------
__device__ float g_qc[BB * HH];          // Wa q + Wa_b + Ua_b
__device__ float g_spart[4 * BB * LK];   // per-nchunk partial scores
__device__ float g_part[16 * BB * HH];   // context partials per 256-l chunk
__device__ float g_wbuf[BB * LK];        // fallback weights output
__device__ float g_cbuf[BB * HH];        // fallback context output

// ================= helpers ===================================================
__device__ __forceinline__ uint32_t smem_u32(const void* p) {
    uint32_t a;
    asm("{ .reg .u64 t; cvta.to.shared.u64 t, %1; cvt.u32.u64 %0, t; }"
        : "=r"(a) : "l"(p));
    return a;
}
__device__ __forceinline__ float fast_tanh(float x) {
    float cx = fminf(fmaxf(x, -15.f), 15.f);
    float e; asm("ex2.approx.f32 %0, %1;" : "=f"(e) : "f"(cx * 2.885390082f));
    float r; asm("rcp.approx.f32 %0, %1;" : "=f"(r) : "f"(e + 1.f));
    return (e - 1.f) * r;
}
__device__ __forceinline__ void cpa16(uint32_t saddr, const void* g) {
    asm volatile("cp.async.cg.shared.global [%0], [%1], 16;" :: "r"(saddr), "l"(g));
}
#define CP_COMMIT() asm volatile("cp.async.commit_group;" ::: "memory")
#define CP_WAIT2()  asm volatile("cp.async.wait_group 2;" ::: "memory")

#define LDSM_X4(r0, r1, r2, r3, addr)                                         \
    asm volatile("ldmatrix.sync.aligned.m8n8.x4.shared.b16 {%0,%1,%2,%3}, [%4];" \
        : "=r"(r0), "=r"(r1), "=r"(r2), "=r"(r3) : "r"(addr))

#define MMA_TF32(d, a, b)                                                     \
    asm volatile(                                                             \
        "mma.sync.aligned.m16n8k8.row.col.f32.tf32.tf32.f32 "                 \
        "{%0,%1,%2,%3}, {%4,%5,%6,%7}, {%8,%9}, {%0,%1,%2,%3};"               \
        : "+f"((d)[0]), "+f"((d)[1]), "+f"((d)[2]), "+f"((d)[3])              \
        : "r"((a)[0]), "r"((a)[1]), "r"((a)[2]), "r"((a)[3]),                 \
          "r"((b)[0]), "r"((b)[1]))

// ---------------- 1) q projection (+ bias folding) --------------------------
__global__ void k_qc(const float* __restrict__ query, const float* __restrict__ Wa_w,
                     const float* __restrict__ Wa_b, const float* __restrict__ Ua_b) {
    __shared__ float qs[HH];
    int b = blockIdx.x, h = threadIdx.x;
    qs[h] = query[b * HH + h];
    __syncthreads();
    float acc = 0.f;
    const float* wr = Wa_w + (size_t)h * HH;
    #pragma unroll 8
    for (int j = 0; j < HH; j++) acc += qs[j] * wr[j];
    g_qc[b * HH + h] = acc + Wa_b[h] + Ua_b[h];
}

// ---------------- 2) tf32 GEMM (cp.async + ldmatrix) + tanh + Va partial -----
// CTA: 128 l-rows x 128 n-cols (n-chunk z), K=512, 3-stage async pipeline.
// smem words: stage s: A@s*8192, B@s*8192+4096 (XOR-swizzled 32w rows)
//             qc@24576 va@24704 red@24832
#define STW 8192                      // words per stage
__global__ __launch_bounds__(256, 2) void k_score_mma(
    const float* __restrict__ keys, const float* __restrict__ Ua_w,
    const float* __restrict__ Va_w, const int* __restrict__ valid) {
    extern __shared__ uint32_t sm[];
    int lt = blockIdx.x, b = blockIdx.y, z = blockIdx.z;
    int l0 = lt * 128;
    int v = valid[b];
    if (l0 >= v) return;

    int tid = threadIdx.x;
    int wid = tid >> 5, lane = tid & 31;
    int mw = wid & 3, nw = wid >> 2;       // warp grid 4(M) x 2(N)
    int g = lane >> 2, tig = lane & 3;
    int n0 = z * 128;
    uint32_t sb = smem_u32(sm);

    float* qc_s = (float*)(sm + 24576);
    float* va_s = (float*)(sm + 24704);
    float* red  = (float*)(sm + 24832);
    if (tid < 128) {
        qc_s[tid] = g_qc[b * HH + n0 + tid];
        va_s[tid] = Va_w[n0 + tid];
    }

    // ---- producer addressing (per thread) ----
    int m8 = tid >> 3, kq = tid & 7;
    int kx = kq ^ (m8 & 7);
    const float* gA = keys + ((size_t)b * LK + l0 + m8) * HH + kq * 4;
    const float* gB = Ua_w + (size_t)(n0 + m8) * HH + kq * 4;
    uint32_t sA = sb + m8 * 128 + kx * 16;          // byte addrs within stage 0

    // ---- ldmatrix addressing (per lane) ----
    uint32_t xp = (lane & 7) << 4;
    uint32_t aRow[2], bRow[4];
    #pragma unroll
    for (int mi = 0; mi < 2; mi++)
        aRow[mi] = (uint32_t)((mw * 32 + mi * 16 + (lane & 7) + ((lane >> 3) & 1) * 8) * 128);
    #pragma unroll
    for (int nb4 = 0; nb4 < 4; nb4++)
        bRow[nb4] = (uint32_t)((nw * 64 + (nb4 * 2 + (lane >> 4)) * 8 + (lane & 7)) * 128);
    uint32_t cAh = (uint32_t)(lane >> 4) << 4;          // A col-half within k-tile
    uint32_t cBh = (uint32_t)((lane >> 3) & 1) << 4;    // B col-half

    float d[2][8][4];
    #pragma unroll
    for (int mi = 0; mi < 2; mi++)
        #pragma unroll
        for (int ni = 0; ni < 8; ni++)
            #pragma unroll
            for (int jj = 0; jj < 4; jj++) d[mi][ni][jj] = 0.f;

    // ---- prologue: issue stages 0..2 ----
    #pragma unroll
    for (int s = 0; s < 3; s++) {
        uint32_t st = sA + s * (STW * 4);
        const float* ga = gA + s * 32;
        const float* gb = gB + s * 32;
        #pragma unroll
        for (int r = 0; r < 4; r++) {
            cpa16(st + r * 4096, ga + (size_t)r * 32 * HH);
            cpa16(st + 16384 + r * 4096, gb + (size_t)r * 32 * HH);
        }
        CP_COMMIT();
    }

    for (int kt = 0; kt < 16; kt++) {
        CP_WAIT2();
        __syncthreads();
        uint32_t sbuf = sb + (kt % 3) * (STW * 4);

        #pragma unroll
        for (int k8 = 0; k8 < 4; k8++) {
            uint32_t cA = (((uint32_t)(k8 * 2) << 4) + cAh) ^ xp;
            uint32_t cB = (((uint32_t)(k8 * 2) << 4) + cBh) ^ xp;
            uint32_t a[2][4], bf[8][2];
            #pragma unroll
            for (int mi = 0; mi < 2; mi++)
                LDSM_X4(a[mi][0], a[mi][1], a[mi][2], a[mi][3],
                        sbuf + aRow[mi] + cA);
            #pragma unroll
            for (int nb4 = 0; nb4 < 4; nb4++)
                LDSM_X4(bf[nb4 * 2][0], bf[nb4 * 2][1],
                        bf[nb4 * 2 + 1][0], bf[nb4 * 2 + 1][1],
                        sbuf + 16384 + bRow[nb4] + cB);
            #pragma unroll
            for (int mi = 0; mi < 2; mi++)
                #pragma unroll
                for (int ni = 0; ni < 8; ni++)
                    MMA_TF32(d[mi][ni], a[mi], bf[ni]);
        }
        __syncthreads();

        if (kt + 3 < 16) {
            uint32_t st = sA + ((kt + 3) % 3) * (STW * 4);
            const float* ga = gA + (kt + 3) * 32;
            const float* gb = gB + (kt + 3) * 32;
            #pragma unroll
            for (int r = 0; r < 4; r++) {
                cpa16(st + r * 4096, ga + (size_t)r * 32 * HH);
                cpa16(st + 16384 + r * 4096, gb + (size_t)r * 32 * HH);
            }
        }
        CP_COMMIT();   // commit every iter (possibly empty) to keep group count in step
    }

    // ---- epilogue: tanh + Va dot, reduce across n ---------------------------
    float rs[2][2] = {{0.f, 0.f}, {0.f, 0.f}};
    #pragma unroll
    for (int mi = 0; mi < 2; mi++)
        #pragma unroll
        for (int ni = 0; ni < 8; ni++)
            #pragma unroll
            for (int jj = 0; jj < 4; jj++) {
                int nl = nw * 64 + ni * 8 + tig * 2 + (jj & 1);
                rs[mi][jj >> 1] += fast_tanh(d[mi][ni][jj] + qc_s[nl]) * va_s[nl];
            }
    #pragma unroll
    for (int mi = 0; mi < 2; mi++)
        #pragma unroll
        for (int hh = 0; hh < 2; hh++) {
            float s = rs[mi][hh];
            s += __shfl_xor_sync(0xffffffffu, s, 1);
            s += __shfl_xor_sync(0xffffffffu, s, 2);
            rs[mi][hh] = s;
        }
    if (tig == 0) {
        #pragma unroll
        for (int mi = 0; mi < 2; mi++)
            #pragma unroll
            for (int hh = 0; hh < 2; hh++) {
                int row = mw * 32 + mi * 16 + hh * 8 + g;
                red[row * 2 + nw] = rs[mi][hh];
            }
    }
    __syncthreads();
    if (tid < 128)
        g_spart[((size_t)z * BB + b) * LK + l0 + tid] = red[tid * 2] + red[tid * 2 + 1];
}

// ---------------- 3) softmax over Lk per batch (sums 4 partials) -------------
__global__ void k_softmax(const float* __restrict__ Va_b, const float* __restrict__ temp,
                          const int* __restrict__ valid, float* __restrict__ w_out) {
    __shared__ float se[LK];
    __shared__ float rbuf[256];
    int b = blockIdx.x, tid = threadIdx.x;
    int v = valid[b];
    float vb = Va_b[0], invT = 1.f / temp[0];
    const float* p0 = g_spart + ((size_t)0 * BB + b) * LK;
    const float* p1 = g_spart + ((size_t)1 * BB + b) * LK;
    const float* p2 = g_spart + ((size_t)2 * BB + b) * LK;
    const float* p3 = g_spart + ((size_t)3 * BB + b) * LK;
    float mx = -1e30f;
    for (int l = tid; l < LK; l += 256) {
        float s = (l < v) ? (p0[l] + p1[l] + p2[l] + p3[l] + vb) * invT : -1e9f;
        se[l] = s; mx = fmaxf(mx, s);
    }
    rbuf[tid] = mx; __syncthreads();
    for (int s = 128; s > 0; s >>= 1) {
        if (tid < s) rbuf[tid] = fmaxf(rbuf[tid], rbuf[tid + s]);
        __syncthreads();
    }
    mx = rbuf[0]; __syncthreads();
    float sum = 0.f;
    for (int l = tid; l < LK; l += 256) { float e = expf(se[l] - mx); se[l] = e; sum += e; }
    rbuf[tid] = sum; __syncthreads();
    for (int s = 128; s > 0; s >>= 1) {
        if (tid < s) rbuf[tid] += rbuf[tid + s];
        __syncthreads();
    }
    float inv = 1.f / rbuf[0];
    for (int l = tid; l < LK; l += 256) w_out[(size_t)b * LK + l] = se[l] * inv;
}

// ---------------- 4) context partials (chunk=256 for occupancy) --------------
__global__ void k_ctx(const float* __restrict__ keys, const float* __restrict__ w,
                      const int* __restrict__ valid) {
    __shared__ float ws[256];
    int b = blockIdx.y;
    int chunk = blockIdx.x;
    int lbase = chunk * 256;
    int h = threadIdx.x;
    int v = valid[b];
    float acc = 0.f;
    if (lbase < v) {
        int lend = min(256, v - lbase);
        if (h < 256) ws[h] = w[(size_t)b * LK + lbase + h];
        __syncthreads();
        const float* kb = keys + ((size_t)b * LK + lbase) * HH + h;
        for (int l = 0; l < lend; l++) acc += ws[l] * kb[(size_t)l * HH];
    }
    g_part[((size_t)chunk * BB + b) * HH + h] = acc;
}

// ---------------- 5) reduce partials -> context ------------------------------
__global__ void k_ctxred(float* __restrict__ ctx_out) {
    int b = blockIdx.x, h = threadIdx.x;
    float s = 0.f;
    #pragma unroll
    for (int c = 0; c < 16; c++) s += g_part[((size_t)c * BB + b) * HH + h];
    ctx_out[b * HH + h] = s;
}

// ---------------- launch ------------------------------------------------------
extern "C" void kernel_launch(void* const* d_in, const int* in_sizes, int n_in,
                              void* d_out, int out_size) {
    const float* query = (const float*)d_in[0];
    const float* keys  = (const float*)d_in[1];
    const float* Wa_w  = (const float*)d_in[2];
    const float* Wa_b  = (const float*)d_in[3];
    const float* Ua_w  = (const float*)d_in[4];
    const float* Ua_b  = (const float*)d_in[5];
    const float* Va_w  = (const float*)d_in[6];
    const float* Va_b  = (const float*)d_in[7];
    const float* temp  = (const float*)d_in[8];
    const int*   valid = (const int*)d_in[9];

    float* out = (float*)d_out;
    float* ctx_out;
    float* w_out;
    void *cb = nullptr, *wb = nullptr;
    cudaGetSymbolAddress(&cb, g_cbuf);
    cudaGetSymbolAddress(&wb, g_wbuf);
    if (out_size >= BB * HH + BB * LK) { ctx_out = out; w_out = out + BB * HH; }
    else if (out_size == BB * LK)      { w_out = out; ctx_out = (float*)cb; }
    else                               { ctx_out = out; w_out = (float*)wb; }

    const int SMEM_SCORE = (24832 + 256 + 64) * 4;   // ~100.8 KB
    cudaFuncSetAttribute(k_score_mma, cudaFuncAttributeMaxDynamicSharedMemorySize,
                         SMEM_SCORE);

    k_qc<<<BB, HH>>>(query, Wa_w, Wa_b, Ua_b);
    k_score_mma<<<dim3(LK / 128, BB, 4), 256, SMEM_SCORE>>>(keys, Ua_w, Va_w, valid);
    k_softmax<<<BB, 256>>>(Va_b, temp, valid, w_out);
    k_ctx<<<dim3(LK / 256, BB), 512>>>(keys, w_out, valid);
    k_ctxred<<<BB, HH>>>(ctx_out);
}

// round 7
// speedup vs baseline: 2.9442x; 1.0382x over previous
#include <cuda_runtime.h>
#include <cuda_fp16.h>
#include <cstdint>
#include <math.h>

#define BB 32
#define LK 4096
#define HH 512

// ---------------- scratch (device globals; no allocations allowed) ----------
__device__ float g_qc[BB * HH];           // Wa q + Wa_b + Ua_b
__device__ float g_spart[4 * BB * LK];    // per-nchunk partial scores
__device__ float g_part[32 * BB * HH];    // context partials per 128-l chunk
__device__ float g_wbuf[BB * LK];         // fallback weights output
__device__ float g_cbuf[BB * HH];         // fallback context output
__device__ __half g_Ub16[4 * 16 * 128 * 32];  // Ua_w fp16, granule-ordered [z][kt][row][c][8]

// ================= helpers ===================================================
__device__ __forceinline__ uint32_t smem_u32(const void* p) {
    uint32_t a;
    asm("{ .reg .u64 t; cvta.to.shared.u64 t, %1; cvt.u32.u64 %0, t; }"
        : "=r"(a) : "l"(p));
    return a;
}
__device__ __forceinline__ float fast_tanh(float x) {
    float cx = fminf(fmaxf(x, -15.f), 15.f);
    float e; asm("ex2.approx.f32 %0, %1;" : "=f"(e) : "f"(cx * 2.885390082f));
    float r; asm("rcp.approx.f32 %0, %1;" : "=f"(r) : "f"(e + 1.f));
    return (e - 1.f) * r;
}
__device__ __forceinline__ void cpa16(uint32_t saddr, const void* g) {
    asm volatile("cp.async.cg.shared.global [%0], [%1], 16;" :: "r"(saddr), "l"(g));
}
#define CP_COMMIT() asm volatile("cp.async.commit_group;" ::: "memory")
#define CP_WAIT2()  asm volatile("cp.async.wait_group 2;" ::: "memory")

#define LDSM_X4(r0, r1, r2, r3, addr)                                         \
    asm volatile("ldmatrix.sync.aligned.m8n8.x4.shared.b16 {%0,%1,%2,%3}, [%4];" \
        : "=r"(r0), "=r"(r1), "=r"(r2), "=r"(r3) : "r"(addr))

#define MMA_F16(d, a, b)                                                      \
    asm volatile(                                                             \
        "mma.sync.aligned.m16n8k16.row.col.f32.f16.f16.f32 "                  \
        "{%0,%1,%2,%3}, {%4,%5,%6,%7}, {%8,%9}, {%0,%1,%2,%3};"               \
        : "+f"((d)[0]), "+f"((d)[1]), "+f"((d)[2]), "+f"((d)[3])              \
        : "r"((a)[0]), "r"((a)[1]), "r"((a)[2]), "r"((a)[3]),                 \
          "r"((b)[0]), "r"((b)[1]))

__device__ __forceinline__ uint32_t pack2(float x, float y) {
    __half2 h = __floats2half2_rn(x, y);
    return *(uint32_t*)&h;
}

// ---------------- 0) pre-convert Ua_w -> fp16 granule layout -----------------
// g_Ub16[((z*16+kt)*128 + row)*32 + c*8 + j] = Ua_w[(z*128+row)*512 + kt*32 + c*8 + j]
__global__ void k_convB(const float* __restrict__ Ua_w) {
    int gid = blockIdx.x * 256 + threadIdx.x;   // granule id, 32768 total
    int c = gid & 3;
    int t = gid >> 2;
    int row = t & 127;
    int kt = (t >> 7) & 15;
    int z = t >> 11;
    const float* src = Ua_w + ((size_t)(z * 128 + row) * HH + kt * 32 + c * 8);
    __half* dst = g_Ub16 + ((size_t)gid * 8);
    #pragma unroll
    for (int j = 0; j < 8; j++) dst[j] = __float2half_rn(src[j]);
}

// ---------------- 1) q projection (+ bias folding) --------------------------
__global__ void k_qc(const float* __restrict__ query, const float* __restrict__ Wa_w,
                     const float* __restrict__ Wa_b, const float* __restrict__ Ua_b) {
    __shared__ float qs[HH];
    int b = blockIdx.x, h = threadIdx.x;
    qs[h] = query[b * HH + h];
    __syncthreads();
    float acc = 0.f;
    const float* wr = Wa_w + (size_t)h * HH;
    #pragma unroll 8
    for (int j = 0; j < HH; j++) acc += qs[j] * wr[j];
    g_qc[b * HH + h] = acc + Wa_b[h] + Ua_b[h];
}

// ---------------- 2) fp16 mma.sync GEMM + tanh + Va partial ------------------
// CTA: 128 l x 128 n (z-chunk), K=512 in 16 K=32 stages.
// B: 4-stage cp.async fp16 (pre-converted). A: reg-prefetch LDG fp32 -> cvt -> STS.
// smem rows: 80B stride (64B data + 16B pad) -> conflict-free ldmatrix.
#define BSTG 10240                 // bytes per B stage (128 rows * 80)
#define AOFF (4 * BSTG)            // 40960
#define QCOFF 51200
#define VAOFF 51712
#define REDOFF 52224
#define SMEM_SCORE 53312
__global__ __launch_bounds__(256, 2) void k_score_mma(
    const float* __restrict__ keys, const float* __restrict__ Va_w,
    const int* __restrict__ valid) {
    extern __shared__ char smem[];
    int lt = blockIdx.x, b = blockIdx.y, z = blockIdx.z;
    int l0 = lt * 128;
    int v = valid[b];
    if (l0 >= v) return;

    int tid = threadIdx.x;
    int wid = tid >> 5, lane = tid & 31;
    int mw = wid & 3, nw = wid >> 2;       // warp grid 4(M) x 2(N)
    int g = lane >> 2, tig = lane & 3;
    int n0 = z * 128;
    uint32_t sb = smem_u32(smem);

    float* qc_s = (float*)(smem + QCOFF);
    float* va_s = (float*)(smem + VAOFF);
    float* red  = (float*)(smem + REDOFF);
    if (tid < 128) {
        qc_s[tid] = g_qc[b * HH + n0 + tid];
        va_s[tid] = Va_w[n0 + tid];
    }

    // ---- producer addressing ----
    int arow = tid >> 1, ah = tid & 1;                 // A: row, k-half (16 floats)
    const float* gA = keys + ((size_t)b * LK + l0 + arow) * HH + ah * 16;
    uint32_t aDst = sb + AOFF + arow * 80 + ah * 32;
    int brow = tid >> 1, bc = (tid & 1) * 2;           // B: 2 granules per thread
    const __half* gBz = g_Ub16 + (size_t)z * (16 * 128 * 32);
    uint32_t bDst0 = sb + brow * 80 + bc * 16;

    // ---- ldmatrix addressing ----
    uint32_t aRow[2], bRow[4];
    #pragma unroll
    for (int mi = 0; mi < 2; mi++)
        aRow[mi] = (uint32_t)((mw * 32 + mi * 16 + ((lane >> 3) & 1) * 8 + (lane & 7)) * 80);
    #pragma unroll
    for (int nb4 = 0; nb4 < 4; nb4++)
        bRow[nb4] = (uint32_t)((nw * 64 + (nb4 * 2 + (lane >> 4)) * 8 + (lane & 7)) * 80);
    uint32_t cAh = (uint32_t)(lane >> 4) << 4;
    uint32_t cBh = (uint32_t)((lane >> 3) & 1) << 4;

    float d[2][8][4];
    #pragma unroll
    for (int mi = 0; mi < 2; mi++)
        #pragma unroll
        for (int ni = 0; ni < 8; ni++)
            #pragma unroll
            for (int jj = 0; jj < 4; jj++) d[mi][ni][jj] = 0.f;

    // ---- prologue: A stage0 -> regs; B stages 0,1,2 via cp.async ----
    float4 pa[4];
    #pragma unroll
    for (int c = 0; c < 4; c++) pa[c] = *(const float4*)(gA + c * 4);
    #pragma unroll
    for (int s = 0; s < 3; s++) {
        const __half* src = gBz + ((size_t)(s * 128 + brow) * 4 + bc) * 8;
        cpa16(bDst0 + s * BSTG, src);
        cpa16(bDst0 + s * BSTG + 16, src + 8);
        CP_COMMIT();
    }

    for (int kt = 0; kt < 16; kt++) {
        CP_WAIT2();
        __syncthreads();
        // STS A_kt (cvt fp32->fp16)
        uint4 q0 = make_uint4(pack2(pa[0].x, pa[0].y), pack2(pa[0].z, pa[0].w),
                              pack2(pa[1].x, pa[1].y), pack2(pa[1].z, pa[1].w));
        uint4 q1 = make_uint4(pack2(pa[2].x, pa[2].y), pack2(pa[2].z, pa[2].w),
                              pack2(pa[3].x, pa[3].y), pack2(pa[3].z, pa[3].w));
        *(uint4*)(smem + AOFF + arow * 80 + ah * 32) = q0;
        *(uint4*)(smem + AOFF + arow * 80 + ah * 32 + 16) = q1;
        // prefetch A_{kt+1}
        if (kt < 15) {
            const float* ga = gA + (kt + 1) * 32;
            #pragma unroll
            for (int c = 0; c < 4; c++) pa[c] = *(const float4*)(ga + c * 4);
        }
        // issue B_{kt+3}
        if (kt + 3 < 16) {
            int s = kt + 3;
            const __half* src = gBz + ((size_t)(s * 128 + brow) * 4 + bc) * 8;
            uint32_t dst = bDst0 + (s & 3) * BSTG;
            cpa16(dst, src);
            cpa16(dst + 16, src + 8);
        }
        CP_COMMIT();
        __syncthreads();

        // ---- compute: 2 k16 groups ----
        uint32_t aBase = sb + AOFF;
        uint32_t bBase = sb + (kt & 3) * BSTG;
        #pragma unroll
        for (int kg = 0; kg < 2; kg++) {
            uint32_t cA = ((uint32_t)(kg * 2) << 4) + cAh;
            uint32_t cB = ((uint32_t)(kg * 2) << 4) + cBh;
            uint32_t a[2][4], bf[8][2];
            #pragma unroll
            for (int mi = 0; mi < 2; mi++)
                LDSM_X4(a[mi][0], a[mi][1], a[mi][2], a[mi][3], aBase + aRow[mi] + cA);
            #pragma unroll
            for (int nb4 = 0; nb4 < 4; nb4++)
                LDSM_X4(bf[nb4 * 2][0], bf[nb4 * 2][1],
                        bf[nb4 * 2 + 1][0], bf[nb4 * 2 + 1][1],
                        bBase + bRow[nb4] + cB);
            #pragma unroll
            for (int mi = 0; mi < 2; mi++)
                #pragma unroll
                for (int ni = 0; ni < 8; ni++)
                    MMA_F16(d[mi][ni], a[mi], bf[ni]);
        }
    }

    // ---- epilogue: tanh + Va dot, reduce across n ---------------------------
    float rs[2][2] = {{0.f, 0.f}, {0.f, 0.f}};
    #pragma unroll
    for (int mi = 0; mi < 2; mi++)
        #pragma unroll
        for (int ni = 0; ni < 8; ni++)
            #pragma unroll
            for (int jj = 0; jj < 4; jj++) {
                int nl = nw * 64 + ni * 8 + tig * 2 + (jj & 1);
                rs[mi][jj >> 1] += fast_tanh(d[mi][ni][jj] + qc_s[nl]) * va_s[nl];
            }
    #pragma unroll
    for (int mi = 0; mi < 2; mi++)
        #pragma unroll
        for (int hh = 0; hh < 2; hh++) {
            float s = rs[mi][hh];
            s += __shfl_xor_sync(0xffffffffu, s, 1);
            s += __shfl_xor_sync(0xffffffffu, s, 2);
            rs[mi][hh] = s;
        }
    if (tig == 0) {
        #pragma unroll
        for (int mi = 0; mi < 2; mi++)
            #pragma unroll
            for (int hh = 0; hh < 2; hh++) {
                int row = mw * 32 + mi * 16 + hh * 8 + g;
                red[row * 2 + nw] = rs[mi][hh];
            }
    }
    __syncthreads();
    if (tid < 128)
        g_spart[((size_t)z * BB + b) * LK + l0 + tid] = red[tid * 2] + red[tid * 2 + 1];
}

// ---------------- 3) softmax over Lk per batch (sums 4 partials) -------------
__global__ void k_softmax(const float* __restrict__ Va_b, const float* __restrict__ temp,
                          const int* __restrict__ valid, float* __restrict__ w_out) {
    __shared__ float se[LK];
    __shared__ float rbuf[1024];
    int b = blockIdx.x, tid = threadIdx.x;
    int v = valid[b];
    float vb = Va_b[0], invT = 1.f / temp[0];
    const float* p0 = g_spart + ((size_t)0 * BB + b) * LK;
    const float* p1 = g_spart + ((size_t)1 * BB + b) * LK;
    const float* p2 = g_spart + ((size_t)2 * BB + b) * LK;
    const float* p3 = g_spart + ((size_t)3 * BB + b) * LK;
    float mx = -1e30f;
    for (int l = tid; l < LK; l += 1024) {
        float s = (l < v) ? (p0[l] + p1[l] + p2[l] + p3[l] + vb) * invT : -1e9f;
        se[l] = s; mx = fmaxf(mx, s);
    }
    rbuf[tid] = mx; __syncthreads();
    for (int s = 512; s > 0; s >>= 1) {
        if (tid < s) rbuf[tid] = fmaxf(rbuf[tid], rbuf[tid + s]);
        __syncthreads();
    }
    mx = rbuf[0]; __syncthreads();
    float sum = 0.f;
    for (int l = tid; l < LK; l += 1024) { float e = expf(se[l] - mx); se[l] = e; sum += e; }
    rbuf[tid] = sum; __syncthreads();
    for (int s = 512; s > 0; s >>= 1) {
        if (tid < s) rbuf[tid] += rbuf[tid + s];
        __syncthreads();
    }
    float inv = 1.f / rbuf[0];
    for (int l = tid; l < LK; l += 1024) w_out[(size_t)b * LK + l] = se[l] * inv;
}

// ---------------- 4) context partials (chunk=128, 4 accumulators) ------------
__global__ void k_ctx(const float* __restrict__ keys, const float* __restrict__ w,
                      const int* __restrict__ valid) {
    __shared__ float ws[128];
    int b = blockIdx.y;
    int chunk = blockIdx.x;
    int lbase = chunk * 128;
    int h = threadIdx.x;
    int v = valid[b];
    float acc = 0.f;
    if (lbase < v) {
        int lend = min(128, v - lbase);
        if (h < 128) ws[h] = w[(size_t)b * LK + lbase + h];
        __syncthreads();
        const float* kb = keys + ((size_t)b * LK + lbase) * HH + h;
        float a0 = 0.f, a1 = 0.f, a2 = 0.f, a3 = 0.f;
        int l = 0;
        for (; l + 4 <= lend; l += 4) {
            a0 += ws[l]     * kb[(size_t)l * HH];
            a1 += ws[l + 1] * kb[(size_t)(l + 1) * HH];
            a2 += ws[l + 2] * kb[(size_t)(l + 2) * HH];
            a3 += ws[l + 3] * kb[(size_t)(l + 3) * HH];
        }
        for (; l < lend; l++) a0 += ws[l] * kb[(size_t)l * HH];
        acc = (a0 + a1) + (a2 + a3);
    }
    g_part[((size_t)chunk * BB + b) * HH + h] = acc;
}

// ---------------- 5) reduce partials -> context ------------------------------
__global__ void k_ctxred(float* __restrict__ ctx_out) {
    int b = blockIdx.x, h = threadIdx.x;
    float s = 0.f;
    #pragma unroll
    for (int c = 0; c < 32; c++) s += g_part[((size_t)c * BB + b) * HH + h];
    ctx_out[b * HH + h] = s;
}

// ---------------- launch ------------------------------------------------------
extern "C" void kernel_launch(void* const* d_in, const int* in_sizes, int n_in,
                              void* d_out, int out_size) {
    const float* query = (const float*)d_in[0];
    const float* keys  = (const float*)d_in[1];
    const float* Wa_w  = (const float*)d_in[2];
    const float* Wa_b  = (const float*)d_in[3];
    const float* Ua_w  = (const float*)d_in[4];
    const float* Ua_b  = (const float*)d_in[5];
    const float* Va_w  = (const float*)d_in[6];
    const float* Va_b  = (const float*)d_in[7];
    const float* temp  = (const float*)d_in[8];
    const int*   valid = (const int*)d_in[9];

    float* out = (float*)d_out;
    float* ctx_out;
    float* w_out;
    void *cb = nullptr, *wb = nullptr;
    cudaGetSymbolAddress(&cb, g_cbuf);
    cudaGetSymbolAddress(&wb, g_wbuf);
    if (out_size >= BB * HH + BB * LK) { ctx_out = out; w_out = out + BB * HH; }
    else if (out_size == BB * LK)      { w_out = out; ctx_out = (float*)cb; }
    else                               { ctx_out = out; w_out = (float*)wb; }

    cudaFuncSetAttribute(k_score_mma, cudaFuncAttributeMaxDynamicSharedMemorySize,
                         SMEM_SCORE);

    k_convB<<<128, 256>>>(Ua_w);
    k_qc<<<BB, HH>>>(query, Wa_w, Wa_b, Ua_b);
    k_score_mma<<<dim3(LK / 128, BB, 4), 256, SMEM_SCORE>>>(keys, Va_w, valid);
    k_softmax<<<BB, 1024>>>(Va_b, temp, valid, w_out);
    k_ctx<<<dim3(LK / 128, BB), 512>>>(keys, w_out, valid);
    k_ctxred<<<BB, HH>>>(ctx_out);
}

// round 8
// speedup vs baseline: 3.0110x; 1.0227x over previous
#include <cuda_runtime.h>
#include <cuda_fp16.h>
#include <cstdint>
#include <math.h>

#define BB 32
#define LK 4096
#define HH 512

// ---------------- scratch (device globals; no allocations allowed) ----------
__device__ float g_qc[BB * HH];           // Wa q + Wa_b + Ua_b
__device__ float g_spart[4 * BB * LK];    // per-nchunk partial scores
__device__ float g_part[32 * BB * HH];    // context partials per 128-l chunk
__device__ float g_wbuf[BB * LK];         // fallback weights output
__device__ float g_cbuf[BB * HH];         // fallback context output
__device__ __half g_Ub16[4 * 16 * 128 * 32];  // Ua_w fp16, granule-ordered [z][kt][row][c][8]

// ================= helpers ===================================================
__device__ __forceinline__ uint32_t smem_u32(const void* p) {
    uint32_t a;
    asm("{ .reg .u64 t; cvta.to.shared.u64 t, %1; cvt.u32.u64 %0, t; }"
        : "=r"(a) : "l"(p));
    return a;
}
__device__ __forceinline__ float fast_tanh(float x) {
    float cx = fminf(fmaxf(x, -15.f), 15.f);
    float e; asm("ex2.approx.f32 %0, %1;" : "=f"(e) : "f"(cx * 2.885390082f));
    float r; asm("rcp.approx.f32 %0, %1;" : "=f"(r) : "f"(e + 1.f));
    return (e - 1.f) * r;
}
__device__ __forceinline__ void cpa16(uint32_t saddr, const void* g) {
    asm volatile("cp.async.cg.shared.global [%0], [%1], 16;" :: "r"(saddr), "l"(g));
}
#define CP_COMMIT() asm volatile("cp.async.commit_group;" ::: "memory")
#define CP_WAIT2()  asm volatile("cp.async.wait_group 2;" ::: "memory")

#define LDSM_X4(r0, r1, r2, r3, addr)                                         \
    asm volatile("ldmatrix.sync.aligned.m8n8.x4.shared.b16 {%0,%1,%2,%3}, [%4];" \
        : "=r"(r0), "=r"(r1), "=r"(r2), "=r"(r3) : "r"(addr))

#define MMA_F16(d, a, b)                                                      \
    asm volatile(                                                             \
        "mma.sync.aligned.m16n8k16.row.col.f32.f16.f16.f32 "                  \
        "{%0,%1,%2,%3}, {%4,%5,%6,%7}, {%8,%9}, {%0,%1,%2,%3};"               \
        : "+f"((d)[0]), "+f"((d)[1]), "+f"((d)[2]), "+f"((d)[3])              \
        : "r"((a)[0]), "r"((a)[1]), "r"((a)[2]), "r"((a)[3]),                 \
          "r"((b)[0]), "r"((b)[1]))

__device__ __forceinline__ uint32_t pack2(float x, float y) {
    __half2 h = __floats2half2_rn(x, y);
    return *(uint32_t*)&h;
}

// ---------------- 0) pre-convert Ua_w -> fp16 granule layout -----------------
__global__ void k_convB(const float* __restrict__ Ua_w) {
    int gid = blockIdx.x * 256 + threadIdx.x;   // granule id, 32768 total
    int c = gid & 3;
    int t = gid >> 2;
    int row = t & 127;
    int kt = (t >> 7) & 15;
    int z = t >> 11;
    const float* src = Ua_w + ((size_t)(z * 128 + row) * HH + kt * 32 + c * 8);
    __half* dst = g_Ub16 + ((size_t)gid * 8);
    #pragma unroll
    for (int j = 0; j < 8; j++) dst[j] = __float2half_rn(src[j]);
}

// ---------------- 1) q projection (+ bias folding) --------------------------
__global__ void k_qc(const float* __restrict__ query, const float* __restrict__ Wa_w,
                     const float* __restrict__ Wa_b, const float* __restrict__ Ua_b) {
    __shared__ float qs[HH];
    int b = blockIdx.x, h = threadIdx.x;
    qs[h] = query[b * HH + h];
    __syncthreads();
    float acc = 0.f;
    const float* wr = Wa_w + (size_t)h * HH;
    #pragma unroll 8
    for (int j = 0; j < HH; j++) acc += qs[j] * wr[j];
    g_qc[b * HH + h] = acc + Wa_b[h] + Ua_b[h];
}

// ---------------- 2) fp16 mma GEMM, single-sync pipelined mainloop -----------
// CTA: 128 l x 128 n (z-chunk), K=512 in 16 K=32 stages.
// B: 4-stage cp.async (pre-converted fp16). A: 3-stage smem, reg-prefetch LDG.
// One __syncthreads per iteration.
#define STG 10240                  // bytes per stage (128 rows * 80)
#define AOFF (4 * STG)             // 40960 (A stages at 40960,51200,61440)
#define QCOFF 71680
#define VAOFF 72192
#define REDOFF 72704
#define SMEM_SCORE 73728
__global__ __launch_bounds__(256, 2) void k_score_mma(
    const float* __restrict__ keys, const float* __restrict__ Va_w,
    const int* __restrict__ valid) {
    extern __shared__ char smem[];
    int lt = blockIdx.x, b = blockIdx.y, z = blockIdx.z;
    int l0 = lt * 128;
    int v = valid[b];
    if (l0 >= v) return;

    int tid = threadIdx.x;
    int wid = tid >> 5, lane = tid & 31;
    int mw = wid & 3, nw = wid >> 2;       // warp grid 4(M) x 2(N)
    int g = lane >> 2, tig = lane & 3;
    int n0 = z * 128;
    uint32_t sb = smem_u32(smem);

    float* qc_s = (float*)(smem + QCOFF);
    float* va_s = (float*)(smem + VAOFF);
    float* red  = (float*)(smem + REDOFF);
    if (tid < 128) {
        qc_s[tid] = g_qc[b * HH + n0 + tid];
        va_s[tid] = Va_w[n0 + tid];
    }

    // ---- producer addressing ----
    int arow = tid >> 1, ah = tid & 1;                 // A: row, k-half (16 floats)
    const float* gA = keys + ((size_t)b * LK + l0 + arow) * HH + ah * 16;
    uint32_t aSt = sb + AOFF + arow * 80 + ah * 32;    // + stage*STG
    int brow = tid >> 1, bc = (tid & 1) * 2;           // B: 2 granules per thread
    const __half* gBz = g_Ub16 + (size_t)z * (16 * 128 * 32);
    uint32_t bDst0 = sb + brow * 80 + bc * 16;

    // ---- ldmatrix addressing ----
    uint32_t aRow[2], bRow[4];
    #pragma unroll
    for (int mi = 0; mi < 2; mi++)
        aRow[mi] = (uint32_t)((mw * 32 + mi * 16 + ((lane >> 3) & 1) * 8 + (lane & 7)) * 80);
    #pragma unroll
    for (int nb4 = 0; nb4 < 4; nb4++)
        bRow[nb4] = (uint32_t)((nw * 64 + (nb4 * 2 + (lane >> 4)) * 8 + (lane & 7)) * 80);
    uint32_t cAh = (uint32_t)(lane >> 4) << 4;
    uint32_t cBh = (uint32_t)((lane >> 3) & 1) << 4;

    float d[2][8][4];
    #pragma unroll
    for (int mi = 0; mi < 2; mi++)
        #pragma unroll
        for (int ni = 0; ni < 8; ni++)
            #pragma unroll
            for (int jj = 0; jj < 4; jj++) d[mi][ni][jj] = 0.f;

    // ---- prologue ----
    float4 pa[4];
    // A stage 0 -> smem buf0
    #pragma unroll
    for (int c = 0; c < 4; c++) pa[c] = *(const float4*)(gA + c * 4);
    {
        uint4 q0 = make_uint4(pack2(pa[0].x, pa[0].y), pack2(pa[0].z, pa[0].w),
                              pack2(pa[1].x, pa[1].y), pack2(pa[1].z, pa[1].w));
        uint4 q1 = make_uint4(pack2(pa[2].x, pa[2].y), pack2(pa[2].z, pa[2].w),
                              pack2(pa[3].x, pa[3].y), pack2(pa[3].z, pa[3].w));
        *(uint4*)(smem + AOFF + arow * 80 + ah * 32) = q0;
        *(uint4*)(smem + AOFF + arow * 80 + ah * 32 + 16) = q1;
    }
    // A stage 1 -> regs
    #pragma unroll
    for (int c = 0; c < 4; c++) pa[c] = *(const float4*)(gA + 32 + c * 4);
    // B stages 0..2
    #pragma unroll
    for (int s = 0; s < 3; s++) {
        const __half* src = gBz + ((size_t)(s * 128 + brow) * 4 + bc) * 8;
        cpa16(bDst0 + s * STG, src);
        cpa16(bDst0 + s * STG + 16, src + 8);
        CP_COMMIT();
    }

    for (int kt = 0; kt < 16; kt++) {
        // 1) STS A(kt+1) from regs into buf (kt+1)%3
        if (kt < 15) {
            uint32_t dst = aSt + ((kt + 1) % 3) * STG;
            uint4 q0 = make_uint4(pack2(pa[0].x, pa[0].y), pack2(pa[0].z, pa[0].w),
                                  pack2(pa[1].x, pa[1].y), pack2(pa[1].z, pa[1].w));
            uint4 q1 = make_uint4(pack2(pa[2].x, pa[2].y), pack2(pa[2].z, pa[2].w),
                                  pack2(pa[3].x, pa[3].y), pack2(pa[3].z, pa[3].w));
            *(uint4*)(smem + (dst - sb)) = q0;
            *(uint4*)(smem + (dst - sb) + 16) = q1;
        }
        // 2) LDG A(kt+2) -> regs
        if (kt < 14) {
            const float* ga = gA + (kt + 2) * 32;
            #pragma unroll
            for (int c = 0; c < 4; c++) pa[c] = *(const float4*)(ga + c * 4);
        }
        // 3) B stage kt ready
        CP_WAIT2();
        // 4) single barrier: orders STS A(kt) (prev iter), cp.async visibility,
        //    and LDSM(kt-1) drain vs upcoming B(kt+3) overwrite
        __syncthreads();
        // 5) issue B(kt+3); always commit to keep group cadence
        if (kt + 3 < 16) {
            int s = kt + 3;
            const __half* src = gBz + ((size_t)(s * 128 + brow) * 4 + bc) * 8;
            uint32_t dst = bDst0 + (s & 3) * STG;
            cpa16(dst, src);
            cpa16(dst + 16, src + 8);
        }
        CP_COMMIT();
        // 6) compute on stage kt
        uint32_t aBase = sb + AOFF + (kt % 3) * STG;
        uint32_t bBase = sb + (kt & 3) * STG;
        #pragma unroll
        for (int kg = 0; kg < 2; kg++) {
            uint32_t cA = ((uint32_t)(kg * 2) << 4) + cAh;
            uint32_t cB = ((uint32_t)(kg * 2) << 4) + cBh;
            uint32_t a[2][4], bf[8][2];
            #pragma unroll
            for (int mi = 0; mi < 2; mi++)
                LDSM_X4(a[mi][0], a[mi][1], a[mi][2], a[mi][3], aBase + aRow[mi] + cA);
            #pragma unroll
            for (int nb4 = 0; nb4 < 4; nb4++)
                LDSM_X4(bf[nb4 * 2][0], bf[nb4 * 2][1],
                        bf[nb4 * 2 + 1][0], bf[nb4 * 2 + 1][1],
                        bBase + bRow[nb4] + cB);
            #pragma unroll
            for (int mi = 0; mi < 2; mi++)
                #pragma unroll
                for (int ni = 0; ni < 8; ni++)
                    MMA_F16(d[mi][ni], a[mi], bf[ni]);
        }
    }

    // ---- epilogue: tanh + Va dot, reduce across n ---------------------------
    float rs[2][2] = {{0.f, 0.f}, {0.f, 0.f}};
    #pragma unroll
    for (int mi = 0; mi < 2; mi++)
        #pragma unroll
        for (int ni = 0; ni < 8; ni++)
            #pragma unroll
            for (int jj = 0; jj < 4; jj++) {
                int nl = nw * 64 + ni * 8 + tig * 2 + (jj & 1);
                rs[mi][jj >> 1] += fast_tanh(d[mi][ni][jj] + qc_s[nl]) * va_s[nl];
            }
    #pragma unroll
    for (int mi = 0; mi < 2; mi++)
        #pragma unroll
        for (int hh = 0; hh < 2; hh++) {
            float s = rs[mi][hh];
            s += __shfl_xor_sync(0xffffffffu, s, 1);
            s += __shfl_xor_sync(0xffffffffu, s, 2);
            rs[mi][hh] = s;
        }
    if (tig == 0) {
        #pragma unroll
        for (int mi = 0; mi < 2; mi++)
            #pragma unroll
            for (int hh = 0; hh < 2; hh++) {
                int row = mw * 32 + mi * 16 + hh * 8 + g;
                red[row * 2 + nw] = rs[mi][hh];
            }
    }
    __syncthreads();
    if (tid < 128)
        g_spart[((size_t)z * BB + b) * LK + l0 + tid] = red[tid * 2] + red[tid * 2 + 1];
}

// ---------------- 3) softmax over Lk per batch (sums 4 partials) -------------
__global__ void k_softmax(const float* __restrict__ Va_b, const float* __restrict__ temp,
                          const int* __restrict__ valid, float* __restrict__ w_out) {
    __shared__ float se[LK];
    __shared__ float rbuf[1024];
    int b = blockIdx.x, tid = threadIdx.x;
    int v = valid[b];
    float vb = Va_b[0], invT = 1.f / temp[0];
    const float* p0 = g_spart + ((size_t)0 * BB + b) * LK;
    const float* p1 = g_spart + ((size_t)1 * BB + b) * LK;
    const float* p2 = g_spart + ((size_t)2 * BB + b) * LK;
    const float* p3 = g_spart + ((size_t)3 * BB + b) * LK;
    float mx = -1e30f;
    for (int l = tid; l < LK; l += 1024) {
        float s = (l < v) ? (p0[l] + p1[l] + p2[l] + p3[l] + vb) * invT : -1e9f;
        se[l] = s; mx = fmaxf(mx, s);
    }
    rbuf[tid] = mx; __syncthreads();
    for (int s = 512; s > 0; s >>= 1) {
        if (tid < s) rbuf[tid] = fmaxf(rbuf[tid], rbuf[tid + s]);
        __syncthreads();
    }
    mx = rbuf[0]; __syncthreads();
    float sum = 0.f;
    for (int l = tid; l < LK; l += 1024) { float e = expf(se[l] - mx); se[l] = e; sum += e; }
    rbuf[tid] = sum; __syncthreads();
    for (int s = 512; s > 0; s >>= 1) {
        if (tid < s) rbuf[tid] += rbuf[tid + s];
        __syncthreads();
    }
    float inv = 1.f / rbuf[0];
    for (int l = tid; l < LK; l += 1024) w_out[(size_t)b * LK + l] = se[l] * inv;
}

// ---------------- 4) context partials (chunk=128, 4 accumulators) ------------
__global__ void k_ctx(const float* __restrict__ keys, const float* __restrict__ w,
                      const int* __restrict__ valid) {
    __shared__ float ws[128];
    int b = blockIdx.y;
    int chunk = blockIdx.x;
    int lbase = chunk * 128;
    int h = threadIdx.x;
    int v = valid[b];
    float acc = 0.f;
    if (lbase < v) {
        int lend = min(128, v - lbase);
        if (h < 128) ws[h] = w[(size_t)b * LK + lbase + h];
        __syncthreads();
        const float* kb = keys + ((size_t)b * LK + lbase) * HH + h;
        float a0 = 0.f, a1 = 0.f, a2 = 0.f, a3 = 0.f;
        int l = 0;
        for (; l + 4 <= lend; l += 4) {
            a0 += ws[l]     * kb[(size_t)l * HH];
            a1 += ws[l + 1] * kb[(size_t)(l + 1) * HH];
            a2 += ws[l + 2] * kb[(size_t)(l + 2) * HH];
            a3 += ws[l + 3] * kb[(size_t)(l + 3) * HH];
        }
        for (; l < lend; l++) a0 += ws[l] * kb[(size_t)l * HH];
        acc = (a0 + a1) + (a2 + a3);
    }
    g_part[((size_t)chunk * BB + b) * HH + h] = acc;
}

// ---------------- 5) reduce partials -> context ------------------------------
__global__ void k_ctxred(float* __restrict__ ctx_out) {
    int b = blockIdx.x, h = threadIdx.x;
    float s = 0.f;
    #pragma unroll
    for (int c = 0; c < 32; c++) s += g_part[((size_t)c * BB + b) * HH + h];
    ctx_out[b * HH + h] = s;
}

// ---------------- launch ------------------------------------------------------
extern "C" void kernel_launch(void* const* d_in, const int* in_sizes, int n_in,
                              void* d_out, int out_size) {
    const float* query = (const float*)d_in[0];
    const float* keys  = (const float*)d_in[1];
    const float* Wa_w  = (const float*)d_in[2];
    const float* Wa_b  = (const float*)d_in[3];
    const float* Ua_w  = (const float*)d_in[4];
    const float* Ua_b  = (const float*)d_in[5];
    const float* Va_w  = (const float*)d_in[6];
    const float* Va_b  = (const float*)d_in[7];
    const float* temp  = (const float*)d_in[8];
    const int*   valid = (const int*)d_in[9];

    float* out = (float*)d_out;
    float* ctx_out;
    float* w_out;
    void *cb = nullptr, *wb = nullptr;
    cudaGetSymbolAddress(&cb, g_cbuf);
    cudaGetSymbolAddress(&wb, g_wbuf);
    if (out_size >= BB * HH + BB * LK) { ctx_out = out; w_out = out + BB * HH; }
    else if (out_size == BB * LK)      { w_out = out; ctx_out = (float*)cb; }
    else                               { ctx_out = out; w_out = (float*)wb; }

    cudaFuncSetAttribute(k_score_mma, cudaFuncAttributeMaxDynamicSharedMemorySize,
                         SMEM_SCORE);

    k_convB<<<128, 256>>>(Ua_w);
    k_qc<<<BB, HH>>>(query, Wa_w, Wa_b, Ua_b);
    k_score_mma<<<dim3(LK / 128, BB, 4), 256, SMEM_SCORE>>>(keys, Va_w, valid);
    k_softmax<<<BB, 1024>>>(Va_b, temp, valid, w_out);
    k_ctx<<<dim3(LK / 128, BB), 512>>>(keys, w_out, valid);
    k_ctxred<<<BB, HH>>>(ctx_out);
}